// round 1
// baseline (speedup 1.0000x reference)
#include <cuda_runtime.h>
#include <math.h>

#define B_   16
#define C_   192
#define H_   128
#define W_   128
#define NF_  192
#define O4_  768      // 4*NF
#define KALL 768      // 192 (x) + 576 (h im2col)
#define CO_T 12       // output channels per block
#define W_T  8        // w positions per block
#define ROWS 48       // 4 gates * CO_T
#define COLS 128      // B_ * W_T
#define KC   48       // K chunk
#define NCHUNK 16     // KALL / KC
#define NTHREADS 192  // 12 row-groups * 16 batches

// Persistent device scratch (no allocations allowed).
// g_Wp2: unified weight matrix, transposed+permuted:
//   g_Wp2[k*768 + (ct*48 + r)] = Wall[o][k],  o = (r&3)*NF + ct*CO_T + (r>>2)
//   k<192: masked 1x1 conv weight; k>=192: U[o][c][tau] with c=(k-192)/3, tau=(k-192)%3
__device__ float g_Wp2[KALL * O4_];
__device__ float g_h[2][B_ * NF_ * W_];
__device__ float g_c[B_ * NF_ * W_];

__global__ void prep_weights(const float* __restrict__ Wf, const float* __restrict__ Uf) {
    int idx = blockIdx.x * blockDim.x + threadIdx.x;
    if (idx >= KALL * O4_) return;
    int k = idx / O4_;
    int j = idx - k * O4_;
    int ct = j / ROWS;
    int r  = j - ct * ROWS;
    int g  = r & 3;
    int co = ct * CO_T + (r >> 2);
    int o  = g * NF_ + co;
    float v;
    if (k < C_) {
        v = Wf[o * C_ + k];
        // mask: rows [0,64) zero cols >=64 ; rows [64,128) zero cols >=128
        if ((o < 64 && k >= 64) || (o >= 64 && o < 128 && k >= 128)) v = 0.0f;
    } else {
        int kk = k - C_;
        int c = kk / 3;
        int tau = kk - c * 3;
        v = Uf[(o * NF_ + c) * 3 + tau];
    }
    g_Wp2[idx] = v;
}

__global__ void init_state(const float* __restrict__ ih, const float* __restrict__ ic) {
    int idx = blockIdx.x * blockDim.x + threadIdx.x;
    if (idx >= B_ * NF_ * W_) return;
    int cw = idx % (NF_ * W_);
    g_h[0][idx] = ih[cw];
    g_c[idx]    = ic[cw];
}

__global__ void __launch_bounds__(NTHREADS, 3)
step_kernel(const float* __restrict__ x, const float* __restrict__ bias,
            float* __restrict__ out, int t) {
    __shared__ __align__(16) float Ws[KC * ROWS];   // [i][r]   9 KB
    __shared__ __align__(16) float As[KC * COLS];   // [i][col] 24 KB

    const int ct = blockIdx.x;          // co tile 0..15
    const int w0 = blockIdx.y * W_T;    // w tile origin
    const int tid = threadIdx.x;
    const int tr  = tid >> 4;           // 0..11 : local co index
    const int tb  = tid & 15;           // 0..15 : batch
    const int p   = t & 1;
    const float* __restrict__ hcur = g_h[p];
    float* __restrict__ hnxt = g_h[p ^ 1];

    const int co = ct * CO_T + tr;

    // Accumulators: 4 gates x 4 col-pairs, packed f32x2 (cols wi=2jp, 2jp+1)
    unsigned long long acc[4][4];
    #pragma unroll
    for (int g = 0; g < 4; ++g) {
        float bv = bias[g * NF_ + co];
        unsigned long long bp;
        asm("mov.b64 %0, {%1, %1};" : "=l"(bp) : "f"(bv));
        #pragma unroll
        for (int jp = 0; jp < 4; ++jp) acc[g][jp] = bp;
    }

    for (int cc = 0; cc < NCHUNK; ++cc) {
        const int kbase = cc * KC;
        __syncthreads();

        // ---- fill weight tile: fully coalesced from permuted g_Wp2 ----
        #pragma unroll 4
        for (int e = tid; e < KC * ROWS; e += NTHREADS) {
            int i = e / ROWS;
            int r = e - i * ROWS;
            Ws[e] = g_Wp2[(kbase + i) * O4_ + ct * ROWS + r];
        }

        // ---- fill activation tile ----
        if (kbase < C_) {
            // x part: k = channel
            #pragma unroll 4
            for (int e = tid; e < KC * COLS; e += NTHREADS) {
                int i   = e >> 7;
                int col = e & 127;
                int b   = col >> 3;
                int wi  = col & 7;
                int c   = kbase + i;
                As[e] = x[((b * C_ + c) * H_ + t) * W_ + w0 + wi];
            }
        } else {
            // h im2col part: k-192 = c*3 + tau
            #pragma unroll 4
            for (int e = tid; e < KC * COLS; e += NTHREADS) {
                int i   = e >> 7;
                int col = e & 127;
                int b   = col >> 3;
                int wi  = col & 7;
                int kk  = kbase - C_ + i;
                int c   = kk / 3;
                int tau = kk - c * 3;
                int w   = w0 + wi + tau - 1;
                float v = 0.0f;
                if (w >= 0 && w < W_) v = hcur[(b * NF_ + c) * W_ + w];
                As[e] = v;
            }
        }
        __syncthreads();

        // ---- FFMA2 micro-kernel: 16 packed FMAs per k ----
        #pragma unroll 4
        for (int k = 0; k < KC; ++k) {
            float4 wv = *reinterpret_cast<const float4*>(&Ws[k * ROWS + tr * 4]);
            unsigned long long wp[4];
            asm("mov.b64 %0, {%1, %1};" : "=l"(wp[0]) : "f"(wv.x));
            asm("mov.b64 %0, {%1, %1};" : "=l"(wp[1]) : "f"(wv.y));
            asm("mov.b64 %0, {%1, %1};" : "=l"(wp[2]) : "f"(wv.z));
            asm("mov.b64 %0, {%1, %1};" : "=l"(wp[3]) : "f"(wv.w));
            const ulonglong2* ap =
                reinterpret_cast<const ulonglong2*>(&As[k * COLS + tb * 8]);
            ulonglong2 av0 = ap[0];
            ulonglong2 av1 = ap[1];
            unsigned long long a[4] = {av0.x, av0.y, av1.x, av1.y};
            #pragma unroll
            for (int g = 0; g < 4; ++g) {
                #pragma unroll
                for (int jp = 0; jp < 4; ++jp) {
                    asm("fma.rn.f32x2 %0, %1, %2, %0;"
                        : "+l"(acc[g][jp]) : "l"(a[jp]), "l"(wp[g]));
                }
            }
        }
    }

    // ---- LSTM pointwise update: this thread owns (co, tb, wi=0..7) entirely ----
    const int sidx = (tb * NF_ + co) * W_ + w0;
    float4 cv0 = *reinterpret_cast<const float4*>(&g_c[sidx]);
    float4 cv1 = *reinterpret_cast<const float4*>(&g_c[sidx + 4]);
    float cold[8] = {cv0.x, cv0.y, cv0.z, cv0.w, cv1.x, cv1.y, cv1.z, cv1.w};
    float cn[8], hn[8];

    #pragma unroll
    for (int jp = 0; jp < 4; ++jp) {
        float gl[4][2];
        #pragma unroll
        for (int g = 0; g < 4; ++g) {
            float lo, hi;
            asm("mov.b64 {%0, %1}, %2;" : "=f"(lo), "=f"(hi) : "l"(acc[g][jp]));
            gl[g][0] = lo; gl[g][1] = hi;
        }
        #pragma unroll
        for (int ln = 0; ln < 2; ++ln) {
            int wi = jp * 2 + ln;
            float ov = __saturatef(fmaf(0.2f, gl[0][ln], 0.5f));
            float fv = __saturatef(fmaf(0.2f, gl[1][ln], 0.5f));
            float iv = __saturatef(fmaf(0.2f, gl[2][ln], 0.5f));
            float gg = tanhf(gl[3][ln]);
            float cnew = fv * cold[wi] + iv * gg;
            cn[wi] = cnew;
            hn[wi] = ov * tanhf(cnew);
        }
    }

    // vectorized 16B stores (sector-efficient even though warp-scattered)
    *reinterpret_cast<float4*>(&g_c[sidx])     = make_float4(cn[0], cn[1], cn[2], cn[3]);
    *reinterpret_cast<float4*>(&g_c[sidx + 4]) = make_float4(cn[4], cn[5], cn[6], cn[7]);
    *reinterpret_cast<float4*>(&hnxt[sidx])     = make_float4(hn[0], hn[1], hn[2], hn[3]);
    *reinterpret_cast<float4*>(&hnxt[sidx + 4]) = make_float4(hn[4], hn[5], hn[6], hn[7]);

    const int oidx = ((tb * NF_ + co) * H_ + t) * W_ + w0;
    *reinterpret_cast<float4*>(&out[oidx])     = make_float4(hn[0], hn[1], hn[2], hn[3]);
    *reinterpret_cast<float4*>(&out[oidx + 4]) = make_float4(hn[4], hn[5], hn[6], hn[7]);
}

extern "C" void kernel_launch(void* const* d_in, const int* in_sizes, int n_in,
                              void* d_out, int out_size) {
    const float* x  = (const float*)d_in[0];
    const float* Wf = (const float*)d_in[1];
    const float* Uf = (const float*)d_in[2];
    const float* bf = (const float*)d_in[3];
    const float* ih = (const float*)d_in[4];
    const float* ic = (const float*)d_in[5];
    float* out = (float*)d_out;

    prep_weights<<<(KALL * O4_ + 255) / 256, 256>>>(Wf, Uf);
    init_state<<<(B_ * NF_ * W_ + 255) / 256, 256>>>(ih, ic);

    dim3 grid(NF_ / CO_T, W_ / W_T);   // 16 x 16 = 256 CTAs
    for (int t = 0; t < H_; ++t) {
        step_kernel<<<grid, NTHREADS>>>(x, bf, out, t);
    }
}

// round 3
// speedup vs baseline: 3.1499x; 3.1499x over previous
#include <cuda_runtime.h>
#include <cstdint>
#include <math.h>

#define B_   16
#define C_   192
#define H_   128
#define W_   128
#define NF_  192
#define O4_  768
#define KALL 768
#define KC   32
#define NCHUNK 24      // 768 / 32
#define NTHREADS 256
#define HW_  (H_ * W_)

// Arch-specific (sm_103a / sm_100a) feature gate: tcgen05 only exists in the
// 'a'-suffixed compile pass. The base compute_103 pass compiles the FFMA2
// fallback body instead.
#if defined(__CUDA_ARCH_FEAT_SM103_ALL) || defined(__CUDA_ARCH_FEAT_SM100_ALL) || defined(__CUDA_ARCH_FEAT_SM101_ALL)
#define TC05 1
#else
#define TC05 0
#endif

// ---- persistent device scratch (no allocs allowed) ----
// g_Wh/g_Wl: permuted+split weights, row r = co*4 + gate, layout [r][k] row-major.
__device__ float g_Wh[O4_ * KALL];
__device__ float g_Wl[O4_ * KALL];
__device__ float g_h[2][B_ * NF_ * W_];
__device__ float g_c[B_ * NF_ * W_];

// ------------------- generic helpers -------------------
static __device__ __forceinline__ uint32_t smem_u32(const void* p) {
    uint32_t a;
    asm("{ .reg .u64 t; cvta.to.shared.u64 t, %1; cvt.u32.u64 %0, t; }" : "=r"(a) : "l"(p));
    return a;
}
static __device__ __forceinline__ float tf32_rna(float v) {
    float r; asm("cvt.rna.tf32.f32 %0, %1;" : "=f"(r) : "f"(v)); return r;
}

#define SW128(o) ((uint32_t)(o) ^ ((((uint32_t)(o)) >> 3) & 0x70u))

// dynamic smem layout (relative to 1024-aligned base):
//   buf0: Ah@0  Al@16K  Bh@32K  Bl@48K   buf1: +64K
#define TILE_AH 0
#define TILE_AL 16384
#define TILE_BH 32768
#define TILE_BL 49152
#define BUF_SZ  65536
#define DSMEM   (1024 + 2 * BUF_SZ)

// ------------------- prep kernels -------------------
__global__ void prep_weights(const float* __restrict__ Wf, const float* __restrict__ Uf) {
    int idx = blockIdx.x * blockDim.x + threadIdx.x;
    if (idx >= O4_ * KALL) return;
    int r = idx / KALL;
    int k = idx - r * KALL;
    int co = r >> 2, g = r & 3;
    int o = g * NF_ + co;
    float v;
    if (k < C_) {
        v = Wf[o * C_ + k];
        if ((o < 64 && k >= 64) || (o >= 64 && o < 128 && k >= 128)) v = 0.0f;
    } else {
        int kk = k - C_;
        int c = kk / 3, tau = kk - 3 * c;
        v = Uf[(o * NF_ + c) * 3 + tau];
    }
    float vh = tf32_rna(v);
    g_Wh[idx] = vh;
    g_Wl[idx] = v - vh;     // exact: vh+vl == v in fp32
}

__global__ void init_state(const float* __restrict__ ih, const float* __restrict__ ic) {
    int idx = blockIdx.x * blockDim.x + threadIdx.x;
    if (idx >= B_ * NF_ * W_) return;
    int cw = idx % (NF_ * W_);
    g_h[0][idx] = ih[cw];
    g_c[idx]    = ic[cw];
}

// ------------------- tcgen05-only helpers (guarded) -------------------
#if TC05
static __device__ __forceinline__ uint32_t elect_one() {
    uint32_t p;
    asm volatile("{ .reg .pred p; elect.sync _|p, 0xFFFFFFFF; selp.b32 %0, 1, 0, p; }" : "=r"(p));
    return p;
}
static __device__ __forceinline__ void mbar_wait(uint32_t mbar, uint32_t parity) {
    asm volatile(
        "{\n\t.reg .pred P;\n\t"
        "WL_%=:\n\t"
        "mbarrier.try_wait.parity.acquire.cta.shared::cta.b64 P, [%0], %1, 0x989680;\n\t"
        "@P bra.uni WD_%=;\n\t"
        "bra.uni WL_%=;\n\t"
        "WD_%=:\n\t}"
        :: "r"(mbar), "r"(parity) : "memory");
}
static __device__ __forceinline__ void mma_tf32_ss(uint32_t d, uint64_t da, uint64_t db,
                                                   uint32_t idesc, uint32_t en) {
    asm volatile(
        "{\n\t.reg .pred p;\n\t"
        "setp.ne.u32 p, %4, 0;\n\t"
        "tcgen05.mma.cta_group::1.kind::tf32 [%0], %1, %2, %3, {%5, %5, %5, %5}, p;\n\t"
        "}"
        :: "r"(d), "l"(da), "l"(db), "r"(idesc), "r"(en), "r"(0u) : "memory");
}
static __device__ __forceinline__ void tc_commit(uint32_t mbar) {
    asm volatile("tcgen05.commit.cta_group::1.mbarrier::arrive::one.shared::cluster.b64 [%0];"
                 :: "r"(mbar) : "memory");
}
#define LDTM_X32(r, addr) \
    asm volatile( \
        "tcgen05.ld.sync.aligned.32x32b.x32.b32 " \
        "{%0, %1, %2, %3, %4, %5, %6, %7, " \
        " %8, %9, %10, %11, %12, %13, %14, %15, " \
        " %16, %17, %18, %19, %20, %21, %22, %23, " \
        " %24, %25, %26, %27, %28, %29, %30, %31}, [%32];" \
        : "=r"((r)[0]),  "=r"((r)[1]),  "=r"((r)[2]),  "=r"((r)[3]), \
          "=r"((r)[4]),  "=r"((r)[5]),  "=r"((r)[6]),  "=r"((r)[7]), \
          "=r"((r)[8]),  "=r"((r)[9]),  "=r"((r)[10]), "=r"((r)[11]), \
          "=r"((r)[12]), "=r"((r)[13]), "=r"((r)[14]), "=r"((r)[15]), \
          "=r"((r)[16]), "=r"((r)[17]), "=r"((r)[18]), "=r"((r)[19]), \
          "=r"((r)[20]), "=r"((r)[21]), "=r"((r)[22]), "=r"((r)[23]), \
          "=r"((r)[24]), "=r"((r)[25]), "=r"((r)[26]), "=r"((r)[27]), \
          "=r"((r)[28]), "=r"((r)[29]), "=r"((r)[30]), "=r"((r)[31]) \
        : "r"(addr))

static constexpr uint64_t DESC_BASE_SW128 =
    (uint64_t(2) << 61) | (uint64_t(1) << 46) | (uint64_t(64) << 32) | (uint64_t(1) << 16);
#define MKDESC(a) (DESC_BASE_SW128 | ((uint64_t)(((uint32_t)(a)) >> 4) & 0x3FFFull))

// idesc: D=F32 (bit4), A=TF32 (2<<7), B=TF32 (2<<10), N=128 (16<<17), M=128 (8<<24)
#define IDESC_TF32 ((1u << 4) | (2u << 7) | (2u << 10) | (16u << 17) | (8u << 24))
#endif  // TC05

// ------------------- step kernel -------------------
__global__ void __launch_bounds__(NTHREADS, 1)
step_kernel(const float* __restrict__ x, const float* __restrict__ bias,
            float* __restrict__ out, int t)
{
    extern __shared__ __align__(16) char dsm[];

    const int tid = threadIdx.x;
    const int mt  = blockIdx.x;          // M tile: permuted rows mt*128..+127 (co block mt*32..+31)
    const int b   = blockIdx.y;          // N tile: batch, cols = w 0..127
    const int p   = t & 1;
    const float* __restrict__ hcur = g_h[p] + b * NF_ * W_;
    float* __restrict__ hnxt = g_h[p ^ 1];

    const uint32_t raw = smem_u32(dsm);
    const uint32_t dbase = (raw + 1023u) & ~1023u;
    char* dptr = dsm + (dbase - raw);

    const float* xb = x + (size_t)b * C_ * HW_ + (size_t)t * W_;

#if TC05
    // ================= Path A: tcgen05 tf32 x3 =================
    __shared__ uint32_t s_tmem;
    __shared__ __align__(8) uint64_t s_mbar[2];
    const int wid = tid >> 5;

    if (wid == 0) {
        asm volatile("tcgen05.alloc.cta_group::1.sync.aligned.shared::cta.b32 [%0], %1;"
                     :: "r"(smem_u32(&s_tmem)), "r"(128u) : "memory");
    }
    if (tid == 0) {
        asm volatile("mbarrier.init.shared.b64 [%0], 1;" :: "r"(smem_u32(&s_mbar[0])) : "memory");
        asm volatile("mbarrier.init.shared.b64 [%0], 1;" :: "r"(smem_u32(&s_mbar[1])) : "memory");
    }
    __syncthreads();
    const uint32_t tmem = s_tmem;
    const uint32_t mb0 = smem_u32(&s_mbar[0]);
    const uint32_t mb1 = smem_u32(&s_mbar[1]);

    for (int cc = 0; cc < NCHUNK; ++cc) {
        const int buf = cc & 1;
        char* tb = dptr + buf * BUF_SZ;
        if (cc >= 2) {
            mbar_wait(buf ? mb1 : mb0, ((cc - 2) >> 1) & 1);
        }
        const int kbase = cc * KC;

        // ---- A tiles (pre-split weights) ----
        {
            const float* wh = g_Wh + (size_t)(mt * 128) * KALL + kbase;
            const float* wl = g_Wl + (size_t)(mt * 128) * KALL + kbase;
            #pragma unroll
            for (int it = 0; it < 4; ++it) {
                int gid = tid + it * NTHREADS;        // 0..1023
                int m = gid >> 3, k4 = gid & 7;
                float4 vh4 = *reinterpret_cast<const float4*>(wh + (size_t)m * KALL + k4 * 4);
                float4 vl4 = *reinterpret_cast<const float4*>(wl + (size_t)m * KALL + k4 * 4);
                uint32_t off = SW128(m * 128 + k4 * 16);
                *reinterpret_cast<float4*>(tb + TILE_AH + off) = vh4;
                *reinterpret_cast<float4*>(tb + TILE_AL + off) = vl4;
            }
        }

        // ---- B tiles (activations, hi/lo split in-register) ----
        if (kbase < C_) {
            const float* xk = xb + (size_t)kbase * HW_;
            #pragma unroll
            for (int it = 0; it < 4; ++it) {
                int gid = tid + it * NTHREADS;
                int k4 = gid & 7, w = gid >> 3;
                float vh[4], vl[4];
                #pragma unroll
                for (int j = 0; j < 4; ++j) {
                    float v = xk[(size_t)(k4 * 4 + j) * HW_ + w];
                    vh[j] = tf32_rna(v);
                    vl[j] = v - vh[j];
                }
                uint32_t off = SW128(w * 128 + k4 * 16);
                *reinterpret_cast<float4*>(tb + TILE_BH + off) = make_float4(vh[0], vh[1], vh[2], vh[3]);
                *reinterpret_cast<float4*>(tb + TILE_BL + off) = make_float4(vl[0], vl[1], vl[2], vl[3]);
            }
        } else {
            const int kk0 = kbase - C_;
            #pragma unroll
            for (int it = 0; it < 4; ++it) {
                int gid = tid + it * NTHREADS;
                int k4 = gid & 7, w = gid >> 3;
                float vh[4], vl[4];
                #pragma unroll
                for (int j = 0; j < 4; ++j) {
                    int kk = kk0 + k4 * 4 + j;
                    int c = kk / 3, tau = kk - 3 * c;
                    int ws = w + tau - 1;
                    float v = ((unsigned)ws < (unsigned)W_) ? hcur[c * W_ + ws] : 0.0f;
                    vh[j] = tf32_rna(v);
                    vl[j] = v - vh[j];
                }
                uint32_t off = SW128(w * 128 + k4 * 16);
                *reinterpret_cast<float4*>(tb + TILE_BH + off) = make_float4(vh[0], vh[1], vh[2], vh[3]);
                *reinterpret_cast<float4*>(tb + TILE_BL + off) = make_float4(vl[0], vl[1], vl[2], vl[3]);
            }
        }
        __syncthreads();

        // ---- issue 12 MMAs (tf32x3: Ah*Bh + Ah*Bl + Al*Bh) ----
        if (wid == 0) {
            asm volatile("fence.proxy.async.shared::cta;" ::: "memory");
            if (elect_one()) {
                uint32_t base = dbase + buf * BUF_SZ;
                uint64_t dAh = MKDESC(base + TILE_AH);
                uint64_t dAl = MKDESC(base + TILE_AL);
                uint64_t dBh = MKDESC(base + TILE_BH);
                uint64_t dBl = MKDESC(base + TILE_BL);
                uint64_t pa[3] = {dAh, dAh, dAl};
                uint64_t pb[3] = {dBh, dBl, dBh};
                #pragma unroll
                for (int ps = 0; ps < 3; ++ps) {
                    #pragma unroll
                    for (int ks = 0; ks < 4; ++ks) {
                        uint32_t en = (cc == 0 && ps == 0 && ks == 0) ? 0u : 1u;
                        mma_tf32_ss(tmem, pa[ps] + ks * 2, pb[ps] + ks * 2, IDESC_TF32, en);
                    }
                }
                tc_commit(buf ? mb1 : mb0);
            }
        }
    }

    // drain both buffers
    mbar_wait(mb0, ((NCHUNK - 2) >> 1) & 1);
    mbar_wait(mb1, ((NCHUNK - 1) >> 1) & 1);
    asm volatile("tcgen05.fence::after_thread_sync;" ::: "memory");
    __syncthreads();

    // ---- epilogue: LDTM -> smem gate re-gather -> LSTM pointwise ----
    float* epi = reinterpret_cast<float*>(dptr);   // [128 rows][33 floats] (padded)
    #pragma unroll 1
    for (int nc = 0; nc < 4; ++nc) {
        if (tid < 128) {
            uint32_t dr[32];
            LDTM_X32(dr, tmem + nc * 32);
            asm volatile("tcgen05.wait::ld.sync.aligned;" ::: "memory");
            #pragma unroll
            for (int c2 = 0; c2 < 32; ++c2)
                epi[tid * 33 + c2] = __uint_as_float(dr[c2]);
        }
        __syncthreads();
        #pragma unroll
        for (int it = 0; it < 4; ++it) {
            int id = tid + it * NTHREADS;     // 0..1023
            int co_l = id >> 5, cs = id & 31;
            int w = nc * 32 + cs;
            int co = mt * 32 + co_l;
            float gv[4];
            #pragma unroll
            for (int g = 0; g < 4; ++g)
                gv[g] = epi[(co_l * 4 + g) * 33 + cs] + bias[g * NF_ + co];
            float ov = __saturatef(fmaf(0.2f, gv[0], 0.5f));
            float fv = __saturatef(fmaf(0.2f, gv[1], 0.5f));
            float iv = __saturatef(fmaf(0.2f, gv[2], 0.5f));
            float gg = tanhf(gv[3]);
            int sidx = (b * NF_ + co) * W_ + w;
            float cold = g_c[sidx];
            float cn = fv * cold + iv * gg;
            float hn = ov * tanhf(cn);
            g_c[sidx] = cn;
            hnxt[sidx] = hn;
            out[((size_t)(b * NF_ + co) * H_ + t) * W_ + w] = hn;
        }
        __syncthreads();
    }

    if (wid == 0) {
        asm volatile("tcgen05.dealloc.cta_group::1.sync.aligned.b32 %0, %1;" :: "r"(tmem), "r"(128u));
        asm volatile("tcgen05.relinquish_alloc_permit.cta_group::1.sync.aligned;");
    }

#else
    // ================= Path B: FFMA2 fallback (base-arch pass) =================
    // Tiles: A [k][m] 32x128 fp32 at TILE_AH, B [k][w] 32x128 fp32 at TILE_BH.
    float* As = reinterpret_cast<float*>(dptr + TILE_AH);
    float* Bs = reinterpret_cast<float*>(dptr + TILE_BH);

    const int mq = tid >> 4;   // m block: rows mq*8..+7 (= co pair 2mq, 2mq+1)
    const int wq = tid & 15;   // w block: wq*8..+7

    // acc[mp][wj]: f32x2 pair over m rows (m0+2mp, m0+2mp+1) at w = wq*8+wj
    unsigned long long acc[4][8];
    #pragma unroll
    for (int i = 0; i < 4; ++i)
        #pragma unroll
        for (int j = 0; j < 8; ++j) acc[i][j] = 0ull;

    for (int cc = 0; cc < NCHUNK; ++cc) {
        const int kbase = cc * KC;
        __syncthreads();

        // ---- A fill: transpose [m][k] -> [k][m], reconstruct full fp32 ----
        {
            const float* wh = g_Wh + (size_t)(mt * 128) * KALL + kbase;
            const float* wl = g_Wl + (size_t)(mt * 128) * KALL + kbase;
            #pragma unroll
            for (int it = 0; it < 4; ++it) {
                int gid = tid + it * NTHREADS;      // 0..1023
                int m = gid >> 3, k4 = gid & 7;     // k = k4*4..+3
                float4 vh4 = *reinterpret_cast<const float4*>(wh + (size_t)m * KALL + k4 * 4);
                float4 vl4 = *reinterpret_cast<const float4*>(wl + (size_t)m * KALL + k4 * 4);
                As[(k4 * 4 + 0) * 128 + m] = vh4.x + vl4.x;
                As[(k4 * 4 + 1) * 128 + m] = vh4.y + vl4.y;
                As[(k4 * 4 + 2) * 128 + m] = vh4.z + vl4.z;
                As[(k4 * 4 + 3) * 128 + m] = vh4.w + vl4.w;
            }
        }

        // ---- B fill: [k][w] ----
        if (kbase < C_) {
            const float* xk = xb + (size_t)kbase * HW_;
            #pragma unroll
            for (int it = 0; it < 4; ++it) {
                int gid = tid + it * NTHREADS;
                int k = gid >> 5, wg = (gid & 31) * 4;
                float4 v = *reinterpret_cast<const float4*>(xk + (size_t)k * HW_ + wg);
                *reinterpret_cast<float4*>(Bs + k * 128 + wg) = v;
            }
        } else {
            const int kk0 = kbase - C_;
            #pragma unroll
            for (int it = 0; it < 4; ++it) {
                int gid = tid + it * NTHREADS;
                int k = gid >> 5, wg = (gid & 31) * 4;
                int kk = kk0 + k;
                int c = kk / 3, tau = kk - 3 * c;
                float v[4];
                #pragma unroll
                for (int j = 0; j < 4; ++j) {
                    int ws = wg + j + tau - 1;
                    v[j] = ((unsigned)ws < (unsigned)W_) ? hcur[c * W_ + ws] : 0.0f;
                }
                *reinterpret_cast<float4*>(Bs + k * 128 + wg) =
                    make_float4(v[0], v[1], v[2], v[3]);
            }
        }
        __syncthreads();

        // ---- FFMA2 micro-kernel ----
        #pragma unroll 4
        for (int k = 0; k < KC; ++k) {
            const ulonglong2* ap =
                reinterpret_cast<const ulonglong2*>(As + k * 128 + mq * 8);
            ulonglong2 a01 = ap[0], a23 = ap[1];
            unsigned long long am[4] = {a01.x, a01.y, a23.x, a23.y};
            const float4* bp = reinterpret_cast<const float4*>(Bs + k * 128 + wq * 8);
            float4 b0 = bp[0], b1 = bp[1];
            float bw[8] = {b0.x, b0.y, b0.z, b0.w, b1.x, b1.y, b1.z, b1.w};
            unsigned long long bb[8];
            #pragma unroll
            for (int j = 0; j < 8; ++j)
                asm("mov.b64 %0, {%1, %1};" : "=l"(bb[j]) : "f"(bw[j]));
            #pragma unroll
            for (int wj = 0; wj < 8; ++wj)
                #pragma unroll
                for (int mp = 0; mp < 4; ++mp)
                    asm("fma.rn.f32x2 %0, %1, %2, %0;"
                        : "+l"(acc[mp][wj]) : "l"(am[mp]), "l"(bb[wj]));
        }
    }

    // ---- epilogue: this thread owns co pair (2mq, 2mq+1), w = wq*8..+7 ----
    #pragma unroll
    for (int cop = 0; cop < 2; ++cop) {
        int co = mt * 32 + 2 * mq + cop;
        float bo = bias[0 * NF_ + co];
        float bf2 = bias[1 * NF_ + co];
        float bi = bias[2 * NF_ + co];
        float bg = bias[3 * NF_ + co];
        #pragma unroll
        for (int wj = 0; wj < 8; ++wj) {
            float g0, g1, g2, g3;
            asm("mov.b64 {%0, %1}, %2;" : "=f"(g0), "=f"(g1) : "l"(acc[cop * 2 + 0][wj]));
            asm("mov.b64 {%0, %1}, %2;" : "=f"(g2), "=f"(g3) : "l"(acc[cop * 2 + 1][wj]));
            float ov = __saturatef(fmaf(0.2f, g0 + bo, 0.5f));
            float fv = __saturatef(fmaf(0.2f, g1 + bf2, 0.5f));
            float iv = __saturatef(fmaf(0.2f, g2 + bi, 0.5f));
            float gg = tanhf(g3 + bg);
            int w = wq * 8 + wj;
            int sidx = (b * NF_ + co) * W_ + w;
            float cold = g_c[sidx];
            float cn = fv * cold + iv * gg;
            float hn = ov * tanhf(cn);
            g_c[sidx] = cn;
            hnxt[sidx] = hn;
            out[((size_t)(b * NF_ + co) * H_ + t) * W_ + w] = hn;
        }
    }
#endif
}

// ------------------- launch -------------------
extern "C" void kernel_launch(void* const* d_in, const int* in_sizes, int n_in,
                              void* d_out, int out_size) {
    const float* x  = (const float*)d_in[0];
    const float* Wf = (const float*)d_in[1];
    const float* Uf = (const float*)d_in[2];
    const float* bf = (const float*)d_in[3];
    const float* ih = (const float*)d_in[4];
    const float* ic = (const float*)d_in[5];
    float* out = (float*)d_out;

    cudaFuncSetAttribute(step_kernel, cudaFuncAttributeMaxDynamicSharedMemorySize, DSMEM);

    prep_weights<<<(O4_ * KALL + 255) / 256, 256>>>(Wf, Uf);
    init_state<<<(B_ * NF_ * W_ + 255) / 256, 256>>>(ih, ic);

    dim3 grid(O4_ / 128, B_);   // 6 x 16 = 96 CTAs
    for (int t = 0; t < H_; ++t) {
        step_kernel<<<grid, NTHREADS, DSMEM>>>(x, bf, out, t);
    }
}